// round 14
// baseline (speedup 1.0000x reference)
#include <cuda_runtime.h>

// UniversalRNN: 2-layer tanh RNN (B=2048, T=512, IN=1, H=64) + FC(64->1).
// R11 resubmit (R12/13 hit infra container failures, never ran): NT=1024
// (32 warps/SM), 14 rows/CTA, tile 2 rows x 2 dims x 16 k per thread.
// Single fused ii-loop shares the h0 chunk between phaseA (Whh0) and
// phaseB (Wih1) and keeps regs <= 64 (hard limit at 1024 thr/SM).

constexpr int Bq  = 2048;
constexpr int Tt  = 512;
constexpr int BBS = 16;    // row slots per CTA (padded)
constexpr int BBR = 14;    // real rows per CTA
constexpr int NT  = 1024;  // threads per CTA (32 warps)
constexpr int HP  = 68;    // padded row pitch (floats)
constexpr int XS  = 65;    // x chunk row pitch

// tanh via ex2/rcp approx: ~1e-6 abs err
__device__ __forceinline__ float fast_tanhf(float x) {
    float e;
    asm("ex2.approx.f32 %0, %1;" : "=f"(e) : "f"(x * 2.8853900817779268f));
    float r;
    asm("rcp.approx.f32 %0, %1;" : "=f"(r) : "f"(e + 1.0f));
    return fmaf(-2.0f, r, 1.0f);
}

// packed 2xf32 fma (sm_100+ PTX only)
__device__ __forceinline__ unsigned long long fma2(
    unsigned long long a, unsigned long long b, unsigned long long c) {
    unsigned long long d;
    asm("fma.rn.f32x2 %0, %1, %2, %3;" : "=l"(d) : "l"(a), "l"(b), "l"(c));
    return d;
}

__device__ __forceinline__ float hsum2(unsigned long long v) {
    return __uint_as_float((unsigned)v) + __uint_as_float((unsigned)(v >> 32));
}

__global__ __launch_bounds__(NT, 1) void rnn_fused_kernel(
    const float* __restrict__ x,      // [B, T, 1]
    const float* __restrict__ Wih0,   // [64, 1]
    const float* __restrict__ Whh0,   // [64, 64]
    const float* __restrict__ bih0,   // [64]
    const float* __restrict__ bhh0,   // [64]
    const float* __restrict__ Wih1,   // [64, 64]
    const float* __restrict__ Whh1,   // [64, 64]
    const float* __restrict__ bih1,   // [64]
    const float* __restrict__ bhh1,   // [64]
    const float* __restrict__ Wfc,    // [1, 64]
    const float* __restrict__ bfc,    // [1]
    float* __restrict__ out)          // [B, 1]
{
    extern __shared__ float sm[];
    float* W0  = sm;                  // Whh0 [64][HP]
    float* Wi1 = W0  + 64 * HP;       // Wih1 [64][HP]
    float* Wh1 = Wi1 + 64 * HP;       // Whh1 [64][HP]
    float* h0s = Wh1 + 64 * HP;       // [2][BBS][HP] double-buffered
    float* h1s = h0s + 2 * BBS * HP;  // [2][BBS][HP]
    float* xs  = h1s + 2 * BBS * HP;  // [BBS][XS]
    float* wfc = xs  + BBS * XS;      // [64]

    const int tx = threadIdx.x;
    const int b0 = blockIdx.x * BBR;

    // ---- stage weights into shared ----
    for (int idx = tx; idx < 64 * 64; idx += NT) {
        int r = idx >> 6, c = idx & 63;
        W0 [r * HP + c] = Whh0[idx];
        Wi1[r * HP + c] = Wih1[idx];
        Wh1[r * HP + c] = Whh1[idx];
    }
    if (tx < 64) wfc[tx] = Wfc[tx];
    for (int idx = tx; idx < 2 * BBS * HP; idx += NT) {
        h0s[idx] = 0.0f;
        h1s[idx] = 0.0f;
    }

    // warp dg owns dims {2dg, 2dg+1}; lane = kq*8+rq: rows {rq, rq+8},
    // k-range [16kq, 16kq+16)
    const int dg   = tx >> 5;        // 0..31
    const int lane = tx & 31;
    const int kq   = lane >> 3;      // 0..3
    const int rq   = lane & 7;       // 0..7
    const int r0 = rq, r1 = rq + 8;
    const int d0 = 2 * dg;
    const int koff = kq * 16;

    float wx0 = Wih0[d0], wx1 = Wih0[d0 + 1];
    float b00 = bih0[d0] + bhh0[d0];
    float b01 = bih0[d0 + 1] + bhh0[d0 + 1];
    float b10 = bih1[d0] + bhh1[d0];
    float b11 = bih1[d0 + 1] + bhh1[d0 + 1];

    __syncthreads();

    int cur = 0;
    // interval i: phaseA computes h0(i) (i<Tt), phaseB computes h1(i-1) (i>=1)
    for (int i = 0; i <= Tt; ++i) {
        if ((i & 63) == 0 && i < Tt) {
            // BBS*64 == NT: exactly one element per thread
            int r = tx >> 6, c = tx & 63;
            float v = 0.0f;
            if (r < BBR && b0 + r < Bq) v = x[(b0 + r) * Tt + i + c];
            xs[r * XS + c] = v;
            __syncthreads();
        }
        const int tc = i & 63;
        const float* h0c = h0s + cur * BBS * HP;        // h0(i-1)
        float*       h0n = h0s + (cur ^ 1) * BBS * HP;  // h0(i)
        const float* h1c = h1s + cur * BBS * HP;        // h1(i-2)
        float*       h1n = h1s + (cur ^ 1) * BBS * HP;  // h1(i-1)

        // accumulators: a[0..3] = phaseA (Whh0.h0), c2[0..3] = phaseB
        // layout: {r0,d0},{r0,d0+1},{r1,d0},{r1,d0+1}
        unsigned long long a[4]  = {0, 0, 0, 0};
        unsigned long long c2[4] = {0, 0, 0, 0};

        #pragma unroll
        for (int ii = 0; ii < 4; ++ii) {
            // h0(i-1) chunk — shared by phaseA (W0) and phaseB (Wi1)
            ulonglong2 g0 = *(const ulonglong2*)(h0c + r0 * HP + koff + 4 * ii);
            ulonglong2 g1 = *(const ulonglong2*)(h0c + r1 * HP + koff + 4 * ii);
            ulonglong2 w0a = *(const ulonglong2*)(W0 + d0 * HP + koff + 4 * ii);
            ulonglong2 w0b = *(const ulonglong2*)(W0 + (d0 + 1) * HP + koff + 4 * ii);
            a[0] = fma2(g0.x, w0a.x, a[0]); a[0] = fma2(g0.y, w0a.y, a[0]);
            a[1] = fma2(g0.x, w0b.x, a[1]); a[1] = fma2(g0.y, w0b.y, a[1]);
            a[2] = fma2(g1.x, w0a.x, a[2]); a[2] = fma2(g1.y, w0a.y, a[2]);
            a[3] = fma2(g1.x, w0b.x, a[3]); a[3] = fma2(g1.y, w0b.y, a[3]);

            ulonglong2 wia = *(const ulonglong2*)(Wi1 + d0 * HP + koff + 4 * ii);
            ulonglong2 wib = *(const ulonglong2*)(Wi1 + (d0 + 1) * HP + koff + 4 * ii);
            c2[0] = fma2(g0.x, wia.x, c2[0]); c2[0] = fma2(g0.y, wia.y, c2[0]);
            c2[1] = fma2(g0.x, wib.x, c2[1]); c2[1] = fma2(g0.y, wib.y, c2[1]);
            c2[2] = fma2(g1.x, wia.x, c2[2]); c2[2] = fma2(g1.y, wia.y, c2[2]);
            c2[3] = fma2(g1.x, wib.x, c2[3]); c2[3] = fma2(g1.y, wib.y, c2[3]);

            ulonglong2 q0 = *(const ulonglong2*)(h1c + r0 * HP + koff + 4 * ii);
            ulonglong2 q1 = *(const ulonglong2*)(h1c + r1 * HP + koff + 4 * ii);
            ulonglong2 wha = *(const ulonglong2*)(Wh1 + d0 * HP + koff + 4 * ii);
            ulonglong2 whb = *(const ulonglong2*)(Wh1 + (d0 + 1) * HP + koff + 4 * ii);
            c2[0] = fma2(q0.x, wha.x, c2[0]); c2[0] = fma2(q0.y, wha.y, c2[0]);
            c2[1] = fma2(q0.x, whb.x, c2[1]); c2[1] = fma2(q0.y, whb.y, c2[1]);
            c2[2] = fma2(q1.x, wha.x, c2[2]); c2[2] = fma2(q1.y, wha.y, c2[2]);
            c2[3] = fma2(q1.x, whb.x, c2[3]); c2[3] = fma2(q1.y, whb.y, c2[3]);
        }

        // ---- reduce + tanh + store ----
        float sa[4], sb[4];
        #pragma unroll
        for (int m = 0; m < 4; ++m) {
            sa[m] = hsum2(a[m]);
            sa[m] += __shfl_xor_sync(0xffffffffu, sa[m], 8);
            sa[m] += __shfl_xor_sync(0xffffffffu, sa[m], 16);
            sb[m] = hsum2(c2[m]);
            sb[m] += __shfl_xor_sync(0xffffffffu, sb[m], 8);
            sb[m] += __shfl_xor_sync(0xffffffffu, sb[m], 16);
        }
        {
            const float xv0 = xs[r0 * XS + tc];
            const float xv1 = xs[r1 * XS + tc];
            float2 u0, u1, v0, v1;
            u0.x = fast_tanhf(fmaf(xv0, wx0, sa[0] + b00));
            u0.y = fast_tanhf(fmaf(xv0, wx1, sa[1] + b01));
            u1.x = fast_tanhf(fmaf(xv1, wx0, sa[2] + b00));
            u1.y = fast_tanhf(fmaf(xv1, wx1, sa[3] + b01));
            v0.x = fast_tanhf(sb[0] + b10);
            v0.y = fast_tanhf(sb[1] + b11);
            v1.x = fast_tanhf(sb[2] + b10);
            v1.y = fast_tanhf(sb[3] + b11);
            if (kq == 0) {
                *(float2*)(h0n + r0 * HP + d0) = u0;
                *(float2*)(h0n + r1 * HP + d0) = u1;
                if (i != 0) {
                    *(float2*)(h1n + r0 * HP + d0) = v0;
                    *(float2*)(h1n + r1 * HP + d0) = v1;
                }
            }
        }
        __syncthreads();
        cur ^= 1;
    }

    // ---- FC head: out[b] = Wfc . h1(Tt-1)[b] + bfc ----
    const float* h1f = h1s + cur * BBS * HP;
    if (tx < BBR && b0 + tx < Bq) {
        float acc = bfc[0];
        #pragma unroll
        for (int k = 0; k < 64; ++k)
            acc = fmaf(h1f[tx * HP + k], wfc[k], acc);
        out[b0 + tx] = acc;
    }
}

extern "C" void kernel_launch(void* const* d_in, const int* in_sizes, int n_in,
                              void* d_out, int out_size) {
    (void)in_sizes; (void)n_in; (void)out_size;
    const float* x    = (const float*)d_in[0];
    const float* Wih0 = (const float*)d_in[1];
    const float* Whh0 = (const float*)d_in[2];
    const float* bih0 = (const float*)d_in[3];
    const float* bhh0 = (const float*)d_in[4];
    const float* Wih1 = (const float*)d_in[5];
    const float* Whh1 = (const float*)d_in[6];
    const float* bih1 = (const float*)d_in[7];
    const float* bhh1 = (const float*)d_in[8];
    const float* Wfc  = (const float*)d_in[9];
    const float* bfc  = (const float*)d_in[10];
    float* out = (float*)d_out;

    constexpr int SMEM_FLOATS = 3 * 64 * HP + 4 * BBS * HP + BBS * XS + 64;
    constexpr int SMEM_BYTES  = SMEM_FLOATS * 4;

    cudaFuncSetAttribute(rnn_fused_kernel,
                         cudaFuncAttributeMaxDynamicSharedMemorySize, SMEM_BYTES);

    constexpr int GRID = (Bq + BBR - 1) / BBR;  // 147 CTAs -> all SMs
    rnn_fused_kernel<<<GRID, NT, SMEM_BYTES>>>(
        x, Wih0, Whh0, bih0, bhh0, Wih1, Whh1, bih1, bhh1, Wfc, bfc, out);
}

// round 15
// speedup vs baseline: 1.4713x; 1.4713x over previous
#include <cuda_runtime.h>

// UniversalRNN: 2-layer tanh RNN (B=2048, T=512, IN=1, H=64) + FC(64->1).
// R15: R10 geometry (NT=512, 16 warps, tile 2r x 4d x 16k, 147 CTAs, one
// barrier/interval via layer pipelining) + reduce-SCATTER tail: each kq
// quarter finalizes dim d0+kq only -> 12 SHFL (was 32), 4 tanh (was 16),
// 4 bias adds (was 16). Scattered STS.32 stores are bank-conflict-free.
// R14 lesson: more warps regressed (issue fell, L1 rose); cut instructions.

constexpr int Bq  = 2048;
constexpr int Tt  = 512;
constexpr int BBS = 16;   // row slots per CTA (padded)
constexpr int BBR = 14;   // real rows per CTA
constexpr int NT  = 512;  // threads per CTA (16 warps)
constexpr int HP  = 68;   // padded row pitch (floats)
constexpr int XS  = 65;   // x chunk row pitch

// tanh via ex2/rcp approx: ~1e-6 abs err
__device__ __forceinline__ float fast_tanhf(float x) {
    float e;
    asm("ex2.approx.f32 %0, %1;" : "=f"(e) : "f"(x * 2.8853900817779268f));
    float r;
    asm("rcp.approx.f32 %0, %1;" : "=f"(r) : "f"(e + 1.0f));
    return fmaf(-2.0f, r, 1.0f);
}

// packed 2xf32 fma (sm_100+ PTX only)
__device__ __forceinline__ unsigned long long fma2(
    unsigned long long a, unsigned long long b, unsigned long long c) {
    unsigned long long d;
    asm("fma.rn.f32x2 %0, %1, %2, %3;" : "=l"(d) : "l"(a), "l"(b), "l"(c));
    return d;
}

__device__ __forceinline__ float hsum2(unsigned long long v) {
    return __uint_as_float((unsigned)v) + __uint_as_float((unsigned)(v >> 32));
}

__global__ __launch_bounds__(NT, 1) void rnn_fused_kernel(
    const float* __restrict__ x,      // [B, T, 1]
    const float* __restrict__ Wih0,   // [64, 1]
    const float* __restrict__ Whh0,   // [64, 64]
    const float* __restrict__ bih0,   // [64]
    const float* __restrict__ bhh0,   // [64]
    const float* __restrict__ Wih1,   // [64, 64]
    const float* __restrict__ Whh1,   // [64, 64]
    const float* __restrict__ bih1,   // [64]
    const float* __restrict__ bhh1,   // [64]
    const float* __restrict__ Wfc,    // [1, 64]
    const float* __restrict__ bfc,    // [1]
    float* __restrict__ out)          // [B, 1]
{
    extern __shared__ float sm[];
    float* W0  = sm;                  // Whh0 [64][HP]
    float* Wi1 = W0  + 64 * HP;       // Wih1 [64][HP]
    float* Wh1 = Wi1 + 64 * HP;       // Whh1 [64][HP]
    float* h0s = Wh1 + 64 * HP;       // [2][BBS][HP] double-buffered
    float* h1s = h0s + 2 * BBS * HP;  // [2][BBS][HP]
    float* xs  = h1s + 2 * BBS * HP;  // [BBS][XS]
    float* wfc = xs  + BBS * XS;      // [64]

    const int tx = threadIdx.x;
    const int b0 = blockIdx.x * BBR;

    // ---- stage weights into shared ----
    for (int idx = tx; idx < 64 * 64; idx += NT) {
        int r = idx >> 6, c = idx & 63;
        W0 [r * HP + c] = Whh0[idx];
        Wi1[r * HP + c] = Wih1[idx];
        Wh1[r * HP + c] = Whh1[idx];
    }
    if (tx < 64) wfc[tx] = Wfc[tx];
    for (int idx = tx; idx < 2 * BBS * HP; idx += NT) {
        h0s[idx] = 0.0f;
        h1s[idx] = 0.0f;
    }

    // warp dg owns dims {4dg..4dg+3}; lane = kq*8+rq: rows {rq, rq+8},
    // k-range [16kq, 16kq+16). After reduce-scatter, this lane finalizes
    // dim dq = d0 + kq for both rows, both phases.
    const int dg   = tx >> 5;
    const int lane = tx & 31;
    const int kq   = lane >> 3;
    const int rq   = lane & 7;
    const int r0 = rq, r1 = rq + 8;
    const int d0 = 4 * dg;
    const int koff = kq * 16;
    const int dq = d0 + kq;          // finalized dim for this lane

    const float wxq = Wih0[dq];
    const float b0q = bih0[dq] + bhh0[dq];
    const float b1q = bih1[dq] + bhh1[dq];
    const bool p0 = (kq & 1) != 0;
    const bool p1 = (kq >> 1) != 0;

    __syncthreads();

    int cur = 0;
    // interval i: phaseA computes h0(i) (i<Tt), phaseB computes h1(i-1) (i>=1)
    for (int i = 0; i <= Tt; ++i) {
        if ((i & 63) == 0 && i < Tt) {
            #pragma unroll
            for (int j = 0; j < (BBS * 64) / NT; ++j) {
                int idx = tx + j * NT;
                int r = idx >> 6, c = idx & 63;
                float v = 0.0f;
                if (r < BBR && b0 + r < Bq) v = x[(b0 + r) * Tt + i + c];
                xs[r * XS + c] = v;
            }
            __syncthreads();
        }
        const int tc = i & 63;
        const float* h0c = h0s + cur * BBS * HP;        // h0(i-1)
        float*       h0n = h0s + (cur ^ 1) * BBS * HP;  // h0(i)
        const float* h1c = h1s + cur * BBS * HP;        // h1(i-2)
        float*       h1n = h1s + (cur ^ 1) * BBS * HP;  // h1(i-1)

        // ---- load h0(i-1) chunk ONCE (shared by phaseA Whh0 and phaseB Wih1)
        ulonglong2 g0[4], g1[4];
        #pragma unroll
        for (int ii = 0; ii < 4; ++ii) {
            g0[ii] = *(const ulonglong2*)(h0c + r0 * HP + koff + 4 * ii);
            g1[ii] = *(const ulonglong2*)(h0c + r1 * HP + koff + 4 * ii);
        }

        // ---- phaseA fma: Whh0 . h0(i-1) ----
        unsigned long long a[8] = {0, 0, 0, 0, 0, 0, 0, 0};
        #pragma unroll
        for (int ii = 0; ii < 4; ++ii) {
            #pragma unroll
            for (int j = 0; j < 4; ++j) {
                ulonglong2 w = *(const ulonglong2*)(W0 + (d0 + j) * HP + koff + 4 * ii);
                a[j]     = fma2(g0[ii].x, w.x, a[j]);
                a[j]     = fma2(g0[ii].y, w.y, a[j]);
                a[4 + j] = fma2(g1[ii].x, w.x, a[4 + j]);
                a[4 + j] = fma2(g1[ii].y, w.y, a[4 + j]);
            }
        }

        // ---- phaseB fma: Whh1 . h1(i-2) + Wih1 . h0(i-1) ----
        unsigned long long c[8] = {0, 0, 0, 0, 0, 0, 0, 0};
        #pragma unroll
        for (int ii = 0; ii < 4; ++ii) {
            ulonglong2 q0 = *(const ulonglong2*)(h1c + r0 * HP + koff + 4 * ii);
            ulonglong2 q1 = *(const ulonglong2*)(h1c + r1 * HP + koff + 4 * ii);
            #pragma unroll
            for (int j = 0; j < 4; ++j) {
                ulonglong2 wh = *(const ulonglong2*)(Wh1 + (d0 + j) * HP + koff + 4 * ii);
                c[j]     = fma2(q0.x, wh.x, c[j]);
                c[j]     = fma2(q0.y, wh.y, c[j]);
                c[4 + j] = fma2(q1.x, wh.x, c[4 + j]);
                c[4 + j] = fma2(q1.y, wh.y, c[4 + j]);
            }
        }
        #pragma unroll
        for (int ii = 0; ii < 4; ++ii) {
            #pragma unroll
            for (int j = 0; j < 4; ++j) {
                ulonglong2 wi = *(const ulonglong2*)(Wi1 + (d0 + j) * HP + koff + 4 * ii);
                c[j]     = fma2(g0[ii].x, wi.x, c[j]);
                c[j]     = fma2(g0[ii].y, wi.y, c[j]);
                c[4 + j] = fma2(g1[ii].x, wi.x, c[4 + j]);
                c[4 + j] = fma2(g1[ii].y, wi.y, c[4 + j]);
            }
        }

        // ---- reduce-SCATTER across kq (lanes xor 8, xor 16) ----
        // sX[rr][j]: per-chunk sums. Round 1 consolidates j-bit0 (keep
        // j&1 == kq&1); round 2 consolidates j-bit1 (keep j>>1 == kq>>1).
        // Result: lane holds totals for dim d0+kq only.
        float sA[2][4], sB[2][4];
        #pragma unroll
        for (int j = 0; j < 4; ++j) {
            sA[0][j] = hsum2(a[j]);
            sA[1][j] = hsum2(a[4 + j]);
            sB[0][j] = hsum2(c[j]);
            sB[1][j] = hsum2(c[4 + j]);
        }
        float tA[2][2], tB[2][2];   // [jj][rr]
        #pragma unroll
        for (int jj = 0; jj < 2; ++jj) {
            #pragma unroll
            for (int rr = 0; rr < 2; ++rr) {
                float loA = sA[rr][2 * jj], hiA = sA[rr][2 * jj + 1];
                float sendA = p0 ? loA : hiA;
                float recvA = __shfl_xor_sync(0xffffffffu, sendA, 8);
                tA[jj][rr] = (p0 ? hiA : loA) + recvA;
                float loB = sB[rr][2 * jj], hiB = sB[rr][2 * jj + 1];
                float sendB = p0 ? loB : hiB;
                float recvB = __shfl_xor_sync(0xffffffffu, sendB, 8);
                tB[jj][rr] = (p0 ? hiB : loB) + recvB;
            }
        }
        float uA[2], uB[2];
        #pragma unroll
        for (int rr = 0; rr < 2; ++rr) {
            float sendA = p1 ? tA[0][rr] : tA[1][rr];
            float recvA = __shfl_xor_sync(0xffffffffu, sendA, 16);
            uA[rr] = (p1 ? tA[1][rr] : tA[0][rr]) + recvA;
            float sendB = p1 ? tB[0][rr] : tB[1][rr];
            float recvB = __shfl_xor_sync(0xffffffffu, sendB, 16);
            uB[rr] = (p1 ? tB[1][rr] : tB[0][rr]) + recvB;
        }

        // ---- finalize: 4 tanh per thread, scattered conflict-free STS.32 ----
        {
            const float xv0 = xs[r0 * XS + tc];
            const float xv1 = xs[r1 * XS + tc];
            float h00 = fast_tanhf(fmaf(xv0, wxq, uA[0] + b0q));
            float h01 = fast_tanhf(fmaf(xv1, wxq, uA[1] + b0q));
            h0n[r0 * HP + dq] = h00;
            h0n[r1 * HP + dq] = h01;
            float h10 = fast_tanhf(uB[0] + b1q);
            float h11 = fast_tanhf(uB[1] + b1q);
            if (i != 0) {
                h1n[r0 * HP + dq] = h10;
                h1n[r1 * HP + dq] = h11;
            }
        }
        __syncthreads();
        cur ^= 1;
    }

    // ---- FC head: out[b] = Wfc . h1(Tt-1)[b] + bfc ----
    const float* h1f = h1s + cur * BBS * HP;
    if (tx < BBR && b0 + tx < Bq) {
        float acc = bfc[0];
        #pragma unroll
        for (int k = 0; k < 64; ++k)
            acc = fmaf(h1f[tx * HP + k], wfc[k], acc);
        out[b0 + tx] = acc;
    }
}

extern "C" void kernel_launch(void* const* d_in, const int* in_sizes, int n_in,
                              void* d_out, int out_size) {
    (void)in_sizes; (void)n_in; (void)out_size;
    const float* x    = (const float*)d_in[0];
    const float* Wih0 = (const float*)d_in[1];
    const float* Whh0 = (const float*)d_in[2];
    const float* bih0 = (const float*)d_in[3];
    const float* bhh0 = (const float*)d_in[4];
    const float* Wih1 = (const float*)d_in[5];
    const float* Whh1 = (const float*)d_in[6];
    const float* bih1 = (const float*)d_in[7];
    const float* bhh1 = (const float*)d_in[8];
    const float* Wfc  = (const float*)d_in[9];
    const float* bfc  = (const float*)d_in[10];
    float* out = (float*)d_out;

    constexpr int SMEM_FLOATS = 3 * 64 * HP + 4 * BBS * HP + BBS * XS + 64;
    constexpr int SMEM_BYTES  = SMEM_FLOATS * 4;

    cudaFuncSetAttribute(rnn_fused_kernel,
                         cudaFuncAttributeMaxDynamicSharedMemorySize, SMEM_BYTES);

    constexpr int GRID = (Bq + BBR - 1) / BBR;  // 147 CTAs -> all SMs
    rnn_fused_kernel<<<GRID, NT, SMEM_BYTES>>>(
        x, Wih0, Whh0, bih0, bhh0, Wih1, Whh1, bih1, bhh1, Wfc, bfc, out);
}